// round 4
// baseline (speedup 1.0000x reference)
#include <cuda_runtime.h>
#include <math.h>

#define T_DATA 40000
#define E_E    2000
#define E_I    400
#define SUB    32
#define T_NO   200
#define NB     17
#define FULLMASK 0xffffffffu

// Output layout (flattened tuple): V_out[40000], Z_out[40000], out_filters[65*200]
#define ZOFF 40000
#define FOFF 80000

// packed fp32x2 FMA (Blackwell FFMA2 — only reachable via PTX)
#define FMA2(d, a, b, c) \
    asm("fma.rn.f32x2 %0, %1, %2, %3;" : "=l"(d) : "l"(a), "l"(b), "l"(c))

// -------- device scratch (allocation-free rule: __device__ globals) --------
__device__ float g_eT[SUB * T_DATA];     // e spike counts, [s][t]
__device__ float g_iT[SUB * T_DATA];     // i spike counts, [s][t]
__device__ float g_syn[T_DATA * SUB];    // conv output, [t][s]
__device__ float g_hf[T_DATA];           // history filter of observed Z
__device__ int   g_maskE[2048];          // [it16][c4][s32] lane masks
__device__ int   g_maskI[512];           // [it4][c4][s32]
__device__ float g_ekern[SUB * T_NO];
__device__ float g_ikern[SUB * T_NO];
__device__ float g_hist[T_NO];
__device__ float g_okern[T_NO];
__device__ float g_A[SUB * SUB];         // C_den * exp(W_sub)
__device__ float g_c[SUB];               // i_kern = c_s * e_kern (if fusible)
__device__ int   g_fused;
__device__ float g_zout[T_DATA];

// =====================================================================
// K0: prep — filters, basis, A matrix, ballot masks, filter block
// =====================================================================
__global__ void prep_kernel(const float* __restrict__ C_den,
                            const float* __restrict__ C_syn_e,
                            const float* __restrict__ C_syn_i,
                            const float* __restrict__ Tau_syn,
                            const float* __restrict__ Delta_syn,
                            const float* __restrict__ W_syn,
                            const float* __restrict__ W_sub,
                            const float* __restrict__ W_hist,
                            const float* __restrict__ Tau_out,
                            const float* __restrict__ W_out,
                            float* __restrict__ d_out)
{
    int tid  = threadIdx.x;
    int gtid = blockIdx.x * blockDim.x + tid;
    int gsz  = gridDim.x * blockDim.x;

    // ballot masks: bit l of mask[(it*4+c)*32+s] <=> column 128*it+4*l+c
    // is assigned to subunit s (C_syn one-hot row nonzero).
    for (int m = gtid; m < 2048; m += gsz) {
        int it = m >> 7, c = (m >> 5) & 3, s = m & 31;
        unsigned msk = 0u;
        #pragma unroll 4
        for (int l = 0; l < 32; l++) {
            int col = 128 * it + 4 * l + c;
            if (col < E_E && C_syn_e[s * E_E + col] != 0.f) msk |= 1u << l;
        }
        g_maskE[m] = (int)msk;
    }
    for (int m = gtid; m < 512; m += gsz) {
        int it = m >> 7, c = (m >> 5) & 3, s = m & 31;
        unsigned msk = 0u;
        #pragma unroll 4
        for (int l = 0; l < 32; l++) {
            int col = 128 * it + 4 * l + c;
            if (col < E_I && C_syn_i[s * E_I + col] != 0.f) msk |= 1u << l;
        }
        g_maskI[m] = (int)msk;
    }

    if (blockIdx.x == 0) {
        // e/i alpha kernels: [sub, T_no]
        for (int i = tid; i < SUB * T_NO; i += blockDim.x) {
            int s = i / T_NO, tt = i % T_NO;
            float te  = fmaxf((float)tt - expf(Delta_syn[s * 2 + 0]), 0.f);
            float tte = te / expf(Tau_syn[s * 2 + 0]);
            float ek  = tte * expf(-tte) * expf(W_syn[s * 2 + 0]);
            float ti  = fmaxf((float)tt - expf(Delta_syn[s * 2 + 1]), 0.f);
            float tti = ti / expf(Tau_syn[s * 2 + 1]);
            float ik  = -tti * expf(-tti) * expf(W_syn[s * 2 + 1]);
            g_ekern[i] = ek;
            g_ikern[i] = ik;
            d_out[FOFF + s * T_NO + tt]         = ek;
            d_out[FOFF + (SUB + s) * T_NO + tt] = ik;
        }
    }
    if (blockIdx.x == 1) {
        // history kernel (cosine basis) + output alpha kernel
        const float PI  = 3.14159274101f;   // fp32(pi)
        const float PI2 = 1.57079637051f;   // fp32(pi/2)
        for (int tt = tid; tt < T_NO; tt += blockDim.x) {
            float raw = 4.0f * logf((float)tt + 1.0f);
            float h = 0.f;
            #pragma unroll
            for (int n = 0; n < NB; n++) {
                float phi = PI2 * (float)n;
                float d = raw - phi;
                float b = (raw >= phi - PI && raw <= phi + PI) ? (0.5f * cosf(d) + 0.5f) : 0.f;
                h += expf(W_hist[n]) * b;
            }
            h = -h;
            g_hist[tt] = h;
            d_out[FOFF + 64 * T_NO + tt] = h;

            float tto = (float)tt / expf(Tau_out[0]);
            g_okern[tt] = tto * expf(-tto) * expf(W_out[0]);
        }
    }
    if (blockIdx.x == 2) {
        for (int i = tid; i < SUB * SUB; i += blockDim.x)
            g_A[i] = C_den[i] * expf(W_sub[i & 31]);
    }
}

// =====================================================================
// K0b: fusibility check — is i_kern[s] proportional to e_kern[s]?
// =====================================================================
__global__ void prep2_kernel()
{
    __shared__ int okArr[SUB];
    int s = threadIdx.x;
    if (s < SUB) {
        float best = 0.f; int jm = 0;
        for (int j = 0; j < T_NO; j++) {
            float a = fabsf(g_ekern[s * T_NO + j]);
            if (a > best) { best = a; jm = j; }
        }
        float c = (best > 0.f) ? g_ikern[s * T_NO + jm] / g_ekern[s * T_NO + jm] : 0.f;
        float maxerr = 0.f, maxi = 0.f;
        for (int j = 0; j < T_NO; j++) {
            float ik = g_ikern[s * T_NO + j];
            float er = fabsf(ik - c * g_ekern[s * T_NO + j]);
            maxerr = fmaxf(maxerr, er);
            maxi   = fmaxf(maxi, fabsf(ik));
        }
        okArr[s] = (best > 0.f) && (maxerr <= 1e-5f * (maxi + 1e-20f));
        g_c[s] = c;
    }
    __syncthreads();
    if (threadIdx.x == 0) {
        int all = 1;
        for (int k = 0; k < SUB; k++) all &= okArr[k];
        g_fused = all;
    }
}

// =====================================================================
// K1: spike projection via ballot+popc (spikes are exactly 1.0, C one-hot
// => projection is a per-subunit bit count). One warp per timestep;
// lane s owns subunit s. Pure streaming, no atomics, no divergence.
// =====================================================================
__global__ void __launch_bounds__(256) accum_kernel(const float* __restrict__ S_e,
                                                    const float* __restrict__ S_i)
{
    __shared__ int   sME[2048];
    __shared__ int   sMI[512];
    __shared__ float tE[8][33];
    __shared__ float tI[8][33];

    int tid  = threadIdx.x;
    int warp = tid >> 5;
    int lane = tid & 31;
    int t = blockIdx.x * 8 + warp;   // 5000 blocks * 8 warps = 40000 exactly

    for (int i = tid; i < 2048; i += 256) sME[i] = g_maskE[i];
    for (int i = tid; i < 512;  i += 256) sMI[i] = g_maskI[i];
    __syncthreads();

    const float4 z4 = make_float4(0.f, 0.f, 0.f, 0.f);
    int accE = 0, accI = 0;

    // ---- excitatory row: 500 float4 across 32 lanes = 16 iterations ----
    {
        const float4* rowE = (const float4*)(S_e + (size_t)t * E_E);
        float4 v[8];
        #pragma unroll 1
        for (int it0 = 0; it0 < 16; it0 += 8) {
            #pragma unroll
            for (int u = 0; u < 8; u++) {
                int k = (it0 + u) * 32 + lane;
                v[u] = (k < 500) ? __ldcs(rowE + k) : z4;
            }
            #pragma unroll
            for (int u = 0; u < 8; u++) {
                int it = it0 + u;
                unsigned bx = __ballot_sync(FULLMASK, v[u].x != 0.f);
                unsigned by = __ballot_sync(FULLMASK, v[u].y != 0.f);
                unsigned bz = __ballot_sync(FULLMASK, v[u].z != 0.f);
                unsigned bw = __ballot_sync(FULLMASK, v[u].w != 0.f);
                accE += __popc(bx & (unsigned)sME[(it * 4 + 0) * 32 + lane]);
                accE += __popc(by & (unsigned)sME[(it * 4 + 1) * 32 + lane]);
                accE += __popc(bz & (unsigned)sME[(it * 4 + 2) * 32 + lane]);
                accE += __popc(bw & (unsigned)sME[(it * 4 + 3) * 32 + lane]);
            }
        }
    }
    // ---- inhibitory row: 100 float4 across 32 lanes = 4 iterations ----
    {
        const float4* rowI = (const float4*)(S_i + (size_t)t * E_I);
        float4 v[4];
        #pragma unroll
        for (int u = 0; u < 4; u++) {
            int k = u * 32 + lane;
            v[u] = (k < 100) ? __ldcs(rowI + k) : z4;
        }
        #pragma unroll
        for (int u = 0; u < 4; u++) {
            unsigned bx = __ballot_sync(FULLMASK, v[u].x != 0.f);
            unsigned by = __ballot_sync(FULLMASK, v[u].y != 0.f);
            unsigned bz = __ballot_sync(FULLMASK, v[u].z != 0.f);
            unsigned bw = __ballot_sync(FULLMASK, v[u].w != 0.f);
            accI += __popc(bx & (unsigned)sMI[(u * 4 + 0) * 32 + lane]);
            accI += __popc(by & (unsigned)sMI[(u * 4 + 1) * 32 + lane]);
            accI += __popc(bz & (unsigned)sMI[(u * 4 + 2) * 32 + lane]);
            accI += __popc(bw & (unsigned)sMI[(u * 4 + 3) * 32 + lane]);
        }
    }

    tE[warp][lane] = (float)accE;
    tI[warp][lane] = (float)accI;
    __syncthreads();

    // staged coalesced store into [s][t] layout (32B segments per subunit row)
    int s  = tid >> 3;
    int tt = tid & 7;
    int tg = blockIdx.x * 8 + tt;
    g_eT[s * T_DATA + tg] = tE[tt][s];
    g_iT[s * T_DATA + tg] = tI[tt][s];
}

// =====================================================================
// K2: depthwise causal conv, 200 taps, FFMA2 register-blocked.
// Fused mode (i_kern = c_s*e_kern): input u_s = e + c_s*i, the two f32x2
// lanes carry TWO SUBUNITS (even planes only) -> half the FMA work.
// Fallback mode: lanes carry (e,i) of one subunit (all 32 planes).
// blockIdx.y == 32 plane computes the history conv of observed Z.
// =====================================================================
#define PH(i) ((i) + ((i) >> 3))
typedef unsigned long long ull;

__global__ void __launch_bounds__(128) conv_kernel(const float* __restrict__ Z)
{
    __shared__ float2 xei[1380];         // also reused as float zs[] for hist plane
    __shared__ float2 kei[T_NO];         // also reused as float sh[] for hist plane

    int tid = threadIdx.x;
    int s = blockIdx.y;
    int tBase = blockIdx.x * 1024;

    if (s < SUB) {
        int fused = g_fused;
        if (fused && (s & 1)) return;    // odd planes idle in fused mode

        if (fused) {
            float c0 = g_c[s], c1 = g_c[s + 1];
            for (int L = tid; L < 1224; L += 128) {
                int t = tBase + L - 200;
                bool ok = (t >= 0) && (t < T_DATA);
                float u0 = 0.f, u1 = 0.f;
                if (ok) {
                    u0 = fmaf(c0, g_iT[s * T_DATA + t],       g_eT[s * T_DATA + t]);
                    u1 = fmaf(c1, g_iT[(s + 1) * T_DATA + t], g_eT[(s + 1) * T_DATA + t]);
                }
                xei[PH(L)] = make_float2(u0, u1);
            }
            for (int j = tid; j < T_NO; j += 128)
                kei[j] = make_float2(g_ekern[s * T_NO + j], g_ekern[(s + 1) * T_NO + j]);
        } else {
            for (int L = tid; L < 1224; L += 128) {
                int t = tBase + L - 200;
                bool ok = (t >= 0) && (t < T_DATA);
                float e = ok ? g_eT[s * T_DATA + t] : 0.f;
                float i = ok ? g_iT[s * T_DATA + t] : 0.f;
                xei[PH(L)] = make_float2(e, i);
            }
            for (int j = tid; j < T_NO; j += 128)
                kei[j] = make_float2(g_ekern[s * T_NO + j], g_ikern[s * T_NO + j]);
        }
        __syncthreads();

        const ull* xp = (const ull*)xei;
        const ull* kp = (const ull*)kei;

        ull acc2[8];
        #pragma unroll
        for (int r = 0; r < 8; r++) acc2[r] = 0ull;   // (0.f, 0.f)

        ull w2[15];
        int b = tid * 8 + 192;               // shared logical base for chunk j0=0
        #pragma unroll
        for (int c = 0; c < 15; c++) w2[c] = xp[PH(b + c)];

        ull kk2[8];
        #pragma unroll 1
        for (int j0 = 0; j0 < 200; j0 += 8) {
            #pragma unroll
            for (int jj = 0; jj < 8; jj++) kk2[jj] = kp[j0 + jj];
            #pragma unroll
            for (int jj = 0; jj < 8; jj++) {
                #pragma unroll
                for (int r = 0; r < 8; r++)
                    FMA2(acc2[r], kk2[jj], w2[r + 7 - jj], acc2[r]);
            }
            if (j0 + 8 < 200) {
                b -= 8;
                #pragma unroll
                for (int c = 14; c >= 8; c--) w2[c] = w2[c - 8];
                #pragma unroll
                for (int c = 0; c < 8; c++) w2[c] = xp[PH(b + c)];
            }
        }

        #pragma unroll
        for (int r = 0; r < 8; r++) {
            int t = tBase + tid * 8 + r;
            if (t < T_DATA) {
                float lo, hi;
                asm("mov.b64 {%0,%1}, %2;" : "=f"(lo), "=f"(hi) : "l"(acc2[r]));
                if (fused) {
                    g_syn[t * SUB + s]     = lo;
                    g_syn[t * SUB + s + 1] = hi;
                } else {
                    g_syn[t * SUB + s] = lo + hi;
                }
            }
        }
    } else {
        // ---- history-conv plane: hf[t] = sum_j hist[j] * Z[t-1-j] ----
        float* zs = (float*)xei;
        float* sh = (float*)kei;
        for (int L = tid; L < 1224; L += 128) {
            int t = tBase + L - 200;
            zs[PH(L)] = (t >= 0 && t < T_DATA) ? Z[t] : 0.f;
        }
        for (int j = tid; j < T_NO; j += 128) sh[j] = g_hist[j];
        __syncthreads();

        float acc[8];
        #pragma unroll
        for (int r = 0; r < 8; r++) acc[r] = 0.f;

        float w[15];
        int b = tid * 8 + 192;
        #pragma unroll
        for (int c = 0; c < 15; c++) w[c] = zs[PH(b + c)];

        float kk[8];
        #pragma unroll 1
        for (int j0 = 0; j0 < 200; j0 += 8) {
            #pragma unroll
            for (int jj = 0; jj < 8; jj++) kk[jj] = sh[j0 + jj];
            #pragma unroll
            for (int jj = 0; jj < 8; jj++) {
                #pragma unroll
                for (int r = 0; r < 8; r++)
                    acc[r] = fmaf(kk[jj], w[r + 7 - jj], acc[r]);
            }
            if (j0 + 8 < 200) {
                b -= 8;
                #pragma unroll
                for (int c = 14; c >= 8; c--) w[c] = w[c - 8];
                #pragma unroll
                for (int c = 0; c < 8; c++) w[c] = zs[PH(b + c)];
            }
        }
        #pragma unroll
        for (int r = 0; r < 8; r++) {
            int t = tBase + tid * 8 + r;
            if (t < T_DATA) g_hf[t] = acc[r];
        }
    }
}

// =====================================================================
// K3: per-timestep tree walk, 2 timesteps/thread for ILP across the
// serial tanh chain. C_den binary tree: <=2 FMAs per node.
// =====================================================================
__global__ void __launch_bounds__(256) tree_kernel(const float* __restrict__ Theta,
                                                   float* __restrict__ d_out)
{
    __shared__ float sA[SUB * SUB];
    __shared__ float sTheta[SUB];

    int tid = threadIdx.x;
    int t0 = blockIdx.x * 256 + tid;

    for (int i = tid; i < SUB * SUB; i += 256) sA[i] = g_A[i];
    if (tid < SUB) sTheta[tid] = Theta[tid];
    __syncthreads();
    if (t0 >= T_DATA / 2) return;
    int t1 = t0 + T_DATA / 2;

    float syn0[SUB], syn1[SUB];
    const float4* sr0 = (const float4*)(g_syn + (size_t)t0 * SUB);
    const float4* sr1 = (const float4*)(g_syn + (size_t)t1 * SUB);
    #pragma unroll
    for (int i = 0; i < 8; i++) {
        float4 a = sr0[i];
        syn0[4*i+0] = a.x; syn0[4*i+1] = a.y; syn0[4*i+2] = a.z; syn0[4*i+3] = a.w;
        float4 b = sr1[i];
        syn1[4*i+0] = b.x; syn1[4*i+1] = b.y; syn1[4*i+2] = b.z; syn1[4*i+3] = b.w;
    }

    float sub0[SUB], sub1[SUB];
    #pragma unroll
    for (int i = 0; i < SUB; i++) { sub0[i] = 0.f; sub1[i] = 0.f; }

    #pragma unroll
    for (int idx = SUB - 1; idx >= 1; --idx) {
        float th = sTheta[idx];
        float c0 = syn0[idx] + th;
        float c1 = syn1[idx] + th;
        if (2 * idx + 1 < SUB) {
            float a = sA[idx * SUB + 2 * idx + 1];
            c0 = fmaf(a, sub0[2 * idx + 1], c0);
            c1 = fmaf(a, sub1[2 * idx + 1], c1);
        }
        if (2 * idx + 2 < SUB) {
            float a = sA[idx * SUB + 2 * idx + 2];
            c0 = fmaf(a, sub0[2 * idx + 2], c0);
            c1 = fmaf(a, sub1[2 * idx + 2], c1);
        }
        sub0[idx] = tanhf(c0);
        sub1[idx] = tanhf(c1);
    }

    float r0 = g_hf[t0] + syn0[0] + sTheta[0];
    float r1 = g_hf[t1] + syn1[0] + sTheta[0];
    r0 = fmaf(sA[1], sub0[1], r0); r0 = fmaf(sA[2], sub0[2], r0);
    r1 = fmaf(sA[1], sub1[1], r1); r1 = fmaf(sA[2], sub1[2], r1);

    float z0 = (r0 > 0.f) ? 1.f : 0.f;
    float z1 = (r1 > 0.f) ? 1.f : 0.f;
    d_out[ZOFF + t0] = z0;  g_zout[t0] = z0;
    d_out[ZOFF + t1] = z1;  g_zout[t1] = z1;
}

// =====================================================================
// K4: output alpha-kernel conv of the spike train Z_out -> V_out
// =====================================================================
__global__ void __launch_bounds__(256) vout_kernel(float* __restrict__ d_out)
{
    __shared__ float ok[T_NO];
    __shared__ float zw[456];

    int tid = threadIdx.x;
    int tBase = blockIdx.x * 256;
    int t = tBase + tid;

    for (int i = tid; i < T_NO; i += 256) ok[i] = g_okern[i];
    for (int i = tid; i < 456; i += 256) {
        int tz = tBase - 200 + i;
        zw[i] = (tz >= 0 && tz < T_DATA) ? g_zout[tz] : 0.f;
    }
    __syncthreads();
    if (t >= T_DATA) return;

    float v = 0.f;
    #pragma unroll 4
    for (int j = 0; j < T_NO; j++) v = fmaf(ok[j], zw[tid + 199 - j], v);
    d_out[t] = v;
}

// =====================================================================
extern "C" void kernel_launch(void* const* d_in, const int* in_sizes, int n_in,
                              void* d_out, int out_size)
{
    const float* S_e      = (const float*)d_in[0];
    const float* S_i      = (const float*)d_in[1];
    const float* Z        = (const float*)d_in[2];
    const float* C_den    = (const float*)d_in[3];
    const float* C_syn_e  = (const float*)d_in[4];
    const float* C_syn_i  = (const float*)d_in[5];
    const float* Tau_syn  = (const float*)d_in[6];
    const float* Delta_syn= (const float*)d_in[7];
    const float* W_syn    = (const float*)d_in[8];
    const float* W_sub    = (const float*)d_in[9];
    const float* W_hist   = (const float*)d_in[10];
    const float* Theta    = (const float*)d_in[11];
    const float* Tau_out  = (const float*)d_in[12];
    const float* W_out    = (const float*)d_in[13];
    float* out = (float*)d_out;

    prep_kernel<<<64, 256>>>(C_den, C_syn_e, C_syn_i, Tau_syn, Delta_syn,
                             W_syn, W_sub, W_hist, Tau_out, W_out, out);

    prep2_kernel<<<1, 32>>>();

    accum_kernel<<<T_DATA / 8, 256>>>(S_e, S_i);

    dim3 cgrid((T_DATA + 1023) / 1024, SUB + 1);   // y==32: history conv plane
    conv_kernel<<<cgrid, 128>>>(Z);

    tree_kernel<<<(T_DATA / 2 + 255) / 256, 256>>>(Theta, out);

    vout_kernel<<<(T_DATA + 255) / 256, 256>>>(out);
}

// round 5
// speedup vs baseline: 1.1145x; 1.1145x over previous
#include <cuda_runtime.h>
#include <math.h>

#define T_DATA 40000
#define E_E    2000
#define E_I    400
#define SUB    32
#define T_NO   200
#define NB     17

// Output layout (flattened tuple): V_out[40000], Z_out[40000], out_filters[65*200]
#define ZOFF 40000
#define FOFF 80000

// packed fp32x2 FMA (Blackwell FFMA2 — only reachable via PTX)
#define FMA2(d, a, b, c) \
    asm("fma.rn.f32x2 %0, %1, %2, %3;" : "=l"(d) : "l"(a), "l"(b), "l"(c))

// -------- device scratch (allocation-free rule: __device__ globals) --------
__device__ float g_eT[SUB * T_DATA];     // e spike counts, [s][t]
__device__ float g_iT[SUB * T_DATA];     // i spike counts, [s][t]
__device__ float g_u[SUB * T_DATA];      // fused input e + c_s*i, [s][t]
__device__ float g_syn[T_DATA * SUB];    // conv output, [t][s]
__device__ float g_hf[T_DATA];           // history filter of observed Z
__device__ int   g_subE[E_E];            // subunit id per excitatory column
__device__ int   g_subI[E_I];
__device__ float g_ekern[SUB * T_NO];
__device__ float g_ikern[SUB * T_NO];
__device__ float g_hist[T_NO];
__device__ float g_okern[T_NO];
__device__ float g_A[SUB * SUB];         // C_den * exp(W_sub)
__device__ float g_c[SUB];               // i_kern = c_s * e_kern (if fusible)
__device__ int   g_fused;
__device__ int   g_Js[SUB];              // truncated tap count per subunit
__device__ int   g_J[16];                // per pair (fused planes)
__device__ float g_zout[T_DATA];

// =====================================================================
// K0: prep — filters, basis, A matrix, column->subunit ids, filter block
// =====================================================================
__global__ void prep_kernel(const float* __restrict__ C_den,
                            const float* __restrict__ C_syn_e,
                            const float* __restrict__ C_syn_i,
                            const float* __restrict__ Tau_syn,
                            const float* __restrict__ Delta_syn,
                            const float* __restrict__ W_syn,
                            const float* __restrict__ W_sub,
                            const float* __restrict__ W_hist,
                            const float* __restrict__ Tau_out,
                            const float* __restrict__ W_out,
                            float* __restrict__ d_out)
{
    int tid  = threadIdx.x;
    int gtid = blockIdx.x * blockDim.x + tid;
    int gsz  = gridDim.x * blockDim.x;

    // one-hot column -> subunit id
    for (int e = gtid; e < E_E; e += gsz) {
        int s = 0;
        #pragma unroll
        for (int k = 0; k < SUB; k++)
            if (C_syn_e[k * E_E + e] != 0.f) s = k;
        g_subE[e] = s;
    }
    for (int e = gtid; e < E_I; e += gsz) {
        int s = 0;
        #pragma unroll
        for (int k = 0; k < SUB; k++)
            if (C_syn_i[k * E_I + e] != 0.f) s = k;
        g_subI[e] = s;
    }

    if (blockIdx.x == 0) {
        // e/i alpha kernels: [sub, T_no]
        for (int i = tid; i < SUB * T_NO; i += blockDim.x) {
            int s = i / T_NO, tt = i % T_NO;
            float te  = fmaxf((float)tt - expf(Delta_syn[s * 2 + 0]), 0.f);
            float tte = te / expf(Tau_syn[s * 2 + 0]);
            float ek  = tte * expf(-tte) * expf(W_syn[s * 2 + 0]);
            float ti  = fmaxf((float)tt - expf(Delta_syn[s * 2 + 1]), 0.f);
            float tti = ti / expf(Tau_syn[s * 2 + 1]);
            float ik  = -tti * expf(-tti) * expf(W_syn[s * 2 + 1]);
            g_ekern[i] = ek;
            g_ikern[i] = ik;
            d_out[FOFF + s * T_NO + tt]         = ek;
            d_out[FOFF + (SUB + s) * T_NO + tt] = ik;
        }
    }
    if (blockIdx.x == 1) {
        // history kernel (cosine basis) + output alpha kernel
        const float PI  = 3.14159274101f;   // fp32(pi)
        const float PI2 = 1.57079637051f;   // fp32(pi/2)
        for (int tt = tid; tt < T_NO; tt += blockDim.x) {
            float raw = 4.0f * logf((float)tt + 1.0f);
            float h = 0.f;
            #pragma unroll
            for (int n = 0; n < NB; n++) {
                float phi = PI2 * (float)n;
                float d = raw - phi;
                float b = (raw >= phi - PI && raw <= phi + PI) ? (0.5f * cosf(d) + 0.5f) : 0.f;
                h += expf(W_hist[n]) * b;
            }
            h = -h;
            g_hist[tt] = h;
            d_out[FOFF + 64 * T_NO + tt] = h;

            float tto = (float)tt / expf(Tau_out[0]);
            g_okern[tt] = tto * expf(-tto) * expf(W_out[0]);
        }
    }
    if (blockIdx.x == 2) {
        for (int i = tid; i < SUB * SUB; i += blockDim.x)
            g_A[i] = C_den[i] * expf(W_sub[i & 31]);
    }
}

// =====================================================================
// K0b: fusibility check (i_kern ∝ e_kern?) + truncated tap supports.
// J_s = smallest multiple of 8 with tail |k| sum <= 1e-7 * total.
// =====================================================================
__global__ void prep2_kernel()
{
    __shared__ int okArr[SUB];
    __shared__ int JsArr[SUB];
    int s = threadIdx.x;
    if (s < SUB) {
        float best = 0.f; int jm = 0;
        for (int j = 0; j < T_NO; j++) {
            float a = fabsf(g_ekern[s * T_NO + j]);
            if (a > best) { best = a; jm = j; }
        }
        float c = (best > 0.f) ? g_ikern[s * T_NO + jm] / g_ekern[s * T_NO + jm] : 0.f;
        float maxerr = 0.f, maxi = 0.f;
        float totE = 0.f, totI = 0.f;
        for (int j = 0; j < T_NO; j++) {
            float ek = g_ekern[s * T_NO + j];
            float ik = g_ikern[s * T_NO + j];
            maxerr = fmaxf(maxerr, fabsf(ik - c * ek));
            maxi   = fmaxf(maxi, fabsf(ik));
            totE  += fabsf(ek);
            totI  += fabsf(ik);
        }
        okArr[s] = (best > 0.f) && (maxerr <= 1e-5f * (maxi + 1e-20f));
        g_c[s] = c;

        float tailE = 0.f, tailI = 0.f;
        int J = T_NO;
        for (int j = T_NO - 1; j >= 8; j--) {
            tailE += fabsf(g_ekern[s * T_NO + j]);
            tailI += fabsf(g_ikern[s * T_NO + j]);
            if (tailE <= 1e-7f * totE && tailI <= 1e-7f * totI) J = j;
        }
        J = (J + 7) & ~7;
        if (J > T_NO) J = T_NO;
        JsArr[s] = J;
        g_Js[s] = J;
    }
    __syncthreads();
    if (threadIdx.x == 0) {
        int all = 1;
        for (int k = 0; k < SUB; k++) all &= okArr[k];
        g_fused = all;
        for (int y = 0; y < 16; y++) {
            int J = JsArr[2 * y] > JsArr[2 * y + 1] ? JsArr[2 * y] : JsArr[2 * y + 1];
            g_J[y] = J;
        }
    }
}

// =====================================================================
// K1: spike projection (streaming, rare shared atomics — measured best).
// One warp per timestep, 8 warps/block. Epilogue also stores the fused
// input u_s = e_s + c_s * i_s.
// =====================================================================
__global__ void __launch_bounds__(256) accum_kernel(const float* __restrict__ S_e,
                                                    const float* __restrict__ S_i)
{
    __shared__ float accE[8][33];
    __shared__ float accI[8][33];
    __shared__ char  ssubE[E_E];
    __shared__ char  ssubI[E_I];
    __shared__ float sc[SUB];

    int tid  = threadIdx.x;
    int warp = tid >> 5;
    int lane = tid & 31;
    int t = blockIdx.x * 8 + warp;   // 5000 blocks * 8 warps = 40000 exactly

    for (int i = tid; i < E_E; i += 256) ssubE[i] = (char)g_subE[i];
    for (int i = tid; i < E_I; i += 256) ssubI[i] = (char)g_subI[i];
    if (tid < SUB) sc[tid] = g_c[tid];
    accE[warp][lane] = 0.f;
    accI[warp][lane] = 0.f;
    __syncthreads();

    const float4 z4 = make_float4(0.f, 0.f, 0.f, 0.f);

    // ---- excitatory row: 500 float4 across 32 lanes = 16 iterations, batch 8 ----
    {
        const float4* rowE = (const float4*)(S_e + (size_t)t * E_E);
        float4 v[8];
        #pragma unroll 1
        for (int it0 = 0; it0 < 16; it0 += 8) {
            #pragma unroll
            for (int u = 0; u < 8; u++) {
                int k = (it0 + u) * 32 + lane;
                v[u] = (k < 500) ? __ldcs(rowE + k) : z4;
            }
            #pragma unroll
            for (int u = 0; u < 8; u++) {
                int e = ((it0 + u) * 32 + lane) * 4;
                if (v[u].x != 0.f) atomicAdd(&accE[warp][(int)ssubE[e + 0]], v[u].x);
                if (v[u].y != 0.f) atomicAdd(&accE[warp][(int)ssubE[e + 1]], v[u].y);
                if (v[u].z != 0.f) atomicAdd(&accE[warp][(int)ssubE[e + 2]], v[u].z);
                if (v[u].w != 0.f) atomicAdd(&accE[warp][(int)ssubE[e + 3]], v[u].w);
            }
        }
    }
    // ---- inhibitory row: 100 float4 across 32 lanes = 4 iterations ----
    {
        const float4* rowI = (const float4*)(S_i + (size_t)t * E_I);
        float4 v[4];
        #pragma unroll
        for (int u = 0; u < 4; u++) {
            int k = u * 32 + lane;
            v[u] = (k < 100) ? __ldcs(rowI + k) : z4;
        }
        #pragma unroll
        for (int u = 0; u < 4; u++) {
            int e = (u * 32 + lane) * 4;
            if (v[u].x != 0.f) atomicAdd(&accI[warp][(int)ssubI[e + 0]], v[u].x);
            if (v[u].y != 0.f) atomicAdd(&accI[warp][(int)ssubI[e + 1]], v[u].y);
            if (v[u].z != 0.f) atomicAdd(&accI[warp][(int)ssubI[e + 2]], v[u].z);
            if (v[u].w != 0.f) atomicAdd(&accI[warp][(int)ssubI[e + 3]], v[u].w);
        }
    }
    __syncthreads();

    // staged coalesced store into [s][t] layout (32B segments per subunit row)
    int s  = tid >> 3;
    int tt = tid & 7;
    int tg = blockIdx.x * 8 + tt;
    float e = accE[tt][s];
    float i = accI[tt][s];
    g_eT[s * T_DATA + tg] = e;
    g_iT[s * T_DATA + tg] = i;
    g_u [s * T_DATA + tg] = fmaf(sc[s], i, e);
}

// =====================================================================
// K2: depthwise causal conv, FFMA2 register-blocked, TRUNCATED taps.
// Fused mode: plane y handles subunits (2y, 2y+1) via u_s and e_kern_s,
// the two f32x2 lanes carry the two subunits, J = g_J[y] taps (~24).
// Fallback: two passes per plane, (e,i) lanes, J = g_Js[s].
// blockIdx.y == 16 computes the 200-tap history conv of observed Z.
// =====================================================================
#define PH(i) ((i) + ((i) >> 3))
typedef unsigned long long ull;

__global__ void __launch_bounds__(128) conv_kernel(const float* __restrict__ Z)
{
    __shared__ float2 xei[1380];         // also reused as float zs[] for hist plane
    __shared__ float2 kei[T_NO];         // also reused as float sh[] for hist plane

    int tid = threadIdx.x;
    int y = blockIdx.y;
    int tBase = blockIdx.x * 1024;

    if (y < 16) {
        int fused = g_fused;
        int npass = fused ? 1 : 2;

        #pragma unroll 1
        for (int p = 0; p < npass; p++) {
            if (p) __syncthreads();      // protect tile before reload

            int J;
            if (fused) {
                int s0 = 2 * y, s1 = s0 + 1;
                J = g_J[y];
                for (int L = tid; L < 1224; L += 128) {
                    int t = tBase + L - 200;
                    bool ok = (t >= 0) && (t < T_DATA);
                    float u0 = ok ? g_u[s0 * T_DATA + t] : 0.f;
                    float u1 = ok ? g_u[s1 * T_DATA + t] : 0.f;
                    xei[PH(L)] = make_float2(u0, u1);
                }
                for (int j = tid; j < T_NO; j += 128)
                    kei[j] = make_float2(g_ekern[s0 * T_NO + j], g_ekern[s1 * T_NO + j]);
            } else {
                int s = 2 * y + p;
                J = g_Js[s];
                for (int L = tid; L < 1224; L += 128) {
                    int t = tBase + L - 200;
                    bool ok = (t >= 0) && (t < T_DATA);
                    float e = ok ? g_eT[s * T_DATA + t] : 0.f;
                    float i = ok ? g_iT[s * T_DATA + t] : 0.f;
                    xei[PH(L)] = make_float2(e, i);
                }
                for (int j = tid; j < T_NO; j += 128)
                    kei[j] = make_float2(g_ekern[s * T_NO + j], g_ikern[s * T_NO + j]);
            }
            __syncthreads();

            const ull* xp = (const ull*)xei;
            const ull* kp = (const ull*)kei;

            ull acc2[8];
            #pragma unroll
            for (int r = 0; r < 8; r++) acc2[r] = 0ull;   // (0.f, 0.f)

            ull w2[15];
            int b = tid * 8 + 192;           // shared logical base for chunk j0=0
            #pragma unroll
            for (int c = 0; c < 15; c++) w2[c] = xp[PH(b + c)];

            ull kk2[8];
            #pragma unroll 1
            for (int j0 = 0; j0 < J; j0 += 8) {
                #pragma unroll
                for (int jj = 0; jj < 8; jj++) kk2[jj] = kp[j0 + jj];
                #pragma unroll
                for (int jj = 0; jj < 8; jj++) {
                    #pragma unroll
                    for (int r = 0; r < 8; r++)
                        FMA2(acc2[r], kk2[jj], w2[r + 7 - jj], acc2[r]);
                }
                if (j0 + 8 < J) {
                    b -= 8;
                    #pragma unroll
                    for (int c = 14; c >= 8; c--) w2[c] = w2[c - 8];
                    #pragma unroll
                    for (int c = 0; c < 8; c++) w2[c] = xp[PH(b + c)];
                }
            }

            #pragma unroll
            for (int r = 0; r < 8; r++) {
                int t = tBase + tid * 8 + r;
                if (t < T_DATA) {
                    float lo, hi;
                    asm("mov.b64 {%0,%1}, %2;" : "=f"(lo), "=f"(hi) : "l"(acc2[r]));
                    if (fused) {
                        g_syn[t * SUB + 2 * y]     = lo;
                        g_syn[t * SUB + 2 * y + 1] = hi;
                    } else {
                        g_syn[t * SUB + 2 * y + p] = lo + hi;
                    }
                }
            }
        }
    } else {
        // ---- history-conv plane: hf[t] = sum_j hist[j] * Z[t-1-j] ----
        float* zs = (float*)xei;
        float* sh = (float*)kei;
        for (int L = tid; L < 1224; L += 128) {
            int t = tBase + L - 200;
            zs[PH(L)] = (t >= 0 && t < T_DATA) ? Z[t] : 0.f;
        }
        for (int j = tid; j < T_NO; j += 128) sh[j] = g_hist[j];
        __syncthreads();

        float acc[8];
        #pragma unroll
        for (int r = 0; r < 8; r++) acc[r] = 0.f;

        float w[15];
        int b = tid * 8 + 192;
        #pragma unroll
        for (int c = 0; c < 15; c++) w[c] = zs[PH(b + c)];

        float kk[8];
        #pragma unroll 1
        for (int j0 = 0; j0 < 200; j0 += 8) {
            #pragma unroll
            for (int jj = 0; jj < 8; jj++) kk[jj] = sh[j0 + jj];
            #pragma unroll
            for (int jj = 0; jj < 8; jj++) {
                #pragma unroll
                for (int r = 0; r < 8; r++)
                    acc[r] = fmaf(kk[jj], w[r + 7 - jj], acc[r]);
            }
            if (j0 + 8 < 200) {
                b -= 8;
                #pragma unroll
                for (int c = 14; c >= 8; c--) w[c] = w[c - 8];
                #pragma unroll
                for (int c = 0; c < 8; c++) w[c] = zs[PH(b + c)];
            }
        }
        #pragma unroll
        for (int r = 0; r < 8; r++) {
            int t = tBase + tid * 8 + r;
            if (t < T_DATA) g_hf[t] = acc[r];
        }
    }
}

// =====================================================================
// K3: per-timestep tree walk, 2 timesteps/thread for ILP across the
// serial tanh chain. C_den binary tree: <=2 FMAs per node.
// =====================================================================
__global__ void __launch_bounds__(256) tree_kernel(const float* __restrict__ Theta,
                                                   float* __restrict__ d_out)
{
    __shared__ float sA[SUB * SUB];
    __shared__ float sTheta[SUB];

    int tid = threadIdx.x;
    int t0 = blockIdx.x * 256 + tid;

    for (int i = tid; i < SUB * SUB; i += 256) sA[i] = g_A[i];
    if (tid < SUB) sTheta[tid] = Theta[tid];
    __syncthreads();
    if (t0 >= T_DATA / 2) return;
    int t1 = t0 + T_DATA / 2;

    float syn0[SUB], syn1[SUB];
    const float4* sr0 = (const float4*)(g_syn + (size_t)t0 * SUB);
    const float4* sr1 = (const float4*)(g_syn + (size_t)t1 * SUB);
    #pragma unroll
    for (int i = 0; i < 8; i++) {
        float4 a = sr0[i];
        syn0[4*i+0] = a.x; syn0[4*i+1] = a.y; syn0[4*i+2] = a.z; syn0[4*i+3] = a.w;
        float4 b = sr1[i];
        syn1[4*i+0] = b.x; syn1[4*i+1] = b.y; syn1[4*i+2] = b.z; syn1[4*i+3] = b.w;
    }

    float sub0[SUB], sub1[SUB];
    #pragma unroll
    for (int i = 0; i < SUB; i++) { sub0[i] = 0.f; sub1[i] = 0.f; }

    #pragma unroll
    for (int idx = SUB - 1; idx >= 1; --idx) {
        float th = sTheta[idx];
        float c0 = syn0[idx] + th;
        float c1 = syn1[idx] + th;
        if (2 * idx + 1 < SUB) {
            float a = sA[idx * SUB + 2 * idx + 1];
            c0 = fmaf(a, sub0[2 * idx + 1], c0);
            c1 = fmaf(a, sub1[2 * idx + 1], c1);
        }
        if (2 * idx + 2 < SUB) {
            float a = sA[idx * SUB + 2 * idx + 2];
            c0 = fmaf(a, sub0[2 * idx + 2], c0);
            c1 = fmaf(a, sub1[2 * idx + 2], c1);
        }
        sub0[idx] = tanhf(c0);
        sub1[idx] = tanhf(c1);
    }

    float r0 = g_hf[t0] + syn0[0] + sTheta[0];
    float r1 = g_hf[t1] + syn1[0] + sTheta[0];
    r0 = fmaf(sA[1], sub0[1], r0); r0 = fmaf(sA[2], sub0[2], r0);
    r1 = fmaf(sA[1], sub1[1], r1); r1 = fmaf(sA[2], sub1[2], r1);

    float z0 = (r0 > 0.f) ? 1.f : 0.f;
    float z1 = (r1 > 0.f) ? 1.f : 0.f;
    d_out[ZOFF + t0] = z0;  g_zout[t0] = z0;
    d_out[ZOFF + t1] = z1;  g_zout[t1] = z1;
}

// =====================================================================
// K4: output alpha-kernel conv of the spike train Z_out -> V_out
// =====================================================================
__global__ void __launch_bounds__(256) vout_kernel(float* __restrict__ d_out)
{
    __shared__ float ok[T_NO];
    __shared__ float zw[456];

    int tid = threadIdx.x;
    int tBase = blockIdx.x * 256;
    int t = tBase + tid;

    for (int i = tid; i < T_NO; i += 256) ok[i] = g_okern[i];
    for (int i = tid; i < 456; i += 256) {
        int tz = tBase - 200 + i;
        zw[i] = (tz >= 0 && tz < T_DATA) ? g_zout[tz] : 0.f;
    }
    __syncthreads();
    if (t >= T_DATA) return;

    float v = 0.f;
    #pragma unroll 4
    for (int j = 0; j < T_NO; j++) v = fmaf(ok[j], zw[tid + 199 - j], v);
    d_out[t] = v;
}

// =====================================================================
extern "C" void kernel_launch(void* const* d_in, const int* in_sizes, int n_in,
                              void* d_out, int out_size)
{
    const float* S_e      = (const float*)d_in[0];
    const float* S_i      = (const float*)d_in[1];
    const float* Z        = (const float*)d_in[2];
    const float* C_den    = (const float*)d_in[3];
    const float* C_syn_e  = (const float*)d_in[4];
    const float* C_syn_i  = (const float*)d_in[5];
    const float* Tau_syn  = (const float*)d_in[6];
    const float* Delta_syn= (const float*)d_in[7];
    const float* W_syn    = (const float*)d_in[8];
    const float* W_sub    = (const float*)d_in[9];
    const float* W_hist   = (const float*)d_in[10];
    const float* Theta    = (const float*)d_in[11];
    const float* Tau_out  = (const float*)d_in[12];
    const float* W_out    = (const float*)d_in[13];
    float* out = (float*)d_out;

    prep_kernel<<<64, 256>>>(C_den, C_syn_e, C_syn_i, Tau_syn, Delta_syn,
                             W_syn, W_sub, W_hist, Tau_out, W_out, out);

    prep2_kernel<<<1, 32>>>();

    accum_kernel<<<T_DATA / 8, 256>>>(S_e, S_i);

    dim3 cgrid((T_DATA + 1023) / 1024, 17);   // 16 pair planes + hist plane
    conv_kernel<<<cgrid, 128>>>(Z);

    tree_kernel<<<(T_DATA / 2 + 255) / 256, 256>>>(Theta, out);

    vout_kernel<<<(T_DATA + 255) / 256, 256>>>(out);
}